// round 13
// baseline (speedup 1.0000x reference)
#include <cuda_runtime.h>

#define NN 50000
#define NE 600000
#define HID 128
#define NG 64
#define NBLK 196        // ceil(50000/256)
#define GEMM_CTAS 782   // ceil(50000/64)

// ---- device scratch (no allocations allowed) ----
__device__ int   g_cnt[3][NN];
__device__ float g_dinv[3][NN];
__device__ int   g_off3[3][NN + 1];
__device__ int   g_cur3[3][NN];
__device__ int   g_bsum3[3][NBLK];
__device__ int   g_bpre3[3][NBLK];
__device__ unsigned short g_csr16[3][NE];
__device__ __align__(16) float g_h[3][NN * HID];
__device__ __align__(16) float g_pool[NG * HID];
__device__ float g_pcnt[NG];
// tf32 hi/lo bit-pattern images of W, row-major [k][n]
__device__ __align__(16) unsigned g_Wh32[3][HID * HID];
__device__ __align__(16) unsigned g_Wl32[3][HID * HID];

__device__ __forceinline__ unsigned to_tf32(float v) {
    unsigned u;
    asm("cvt.rna.tf32.f32 %0, %1;" : "=r"(u) : "f"(v));
    return u;
}

// ---------------- init ----------------
__global__ void k_zero() {
    int i = blockIdx.x * blockDim.x + threadIdx.x;
    if (i < NN) { g_cnt[0][i] = 0; g_cnt[1][i] = 0; g_cnt[2][i] = 0; }
    if (i < NG * HID) g_pool[i] = 0.0f;
    if (i < NG) g_pcnt[i] = 0.0f;
}

// ---------------- W prep: f32 -> tf32 hi/lo bit images ----------------
__global__ void k_prepW(const float* __restrict__ W1,
                        const float* __restrict__ W2,
                        const float* __restrict__ W3) {
    int sel = blockIdx.x >> 6;
    int idx = (blockIdx.x & 63) * 256 + threadIdx.x;   // 0..16383
    const float* W = sel == 0 ? W1 : (sel == 1 ? W2 : W3);
    float v = W[idx];
    unsigned uh = to_tf32(v);
    float lo = v - __uint_as_float(uh);
    g_Wh32[sel][idx] = uh;
    g_Wl32[sel][idx] = to_tf32(lo);
}

// ---------------- degree histogram ----------------
__global__ void k_hist(const int* __restrict__ ei,
                       const int* __restrict__ em) {
    int e = blockIdx.x * blockDim.x + threadIdx.x;
    if (e >= NE) return;
    int d = ei[NE + e];
    int m = em[e];
    atomicAdd(&g_cnt[0][d], 1);
    if (m == 1) atomicAdd(&g_cnt[1][d], 1);
    else if (m == 2) atomicAdd(&g_cnt[2][d], 1);
}

// ---------------- scan pass A: per-block sums (3 channels) ----------------
__global__ void k_scanA() {
    int i = blockIdx.x * 256 + threadIdx.x;
    int lane = threadIdx.x & 31, warp = threadIdx.x >> 5;
    __shared__ int ws[3][8];
#pragma unroll
    for (int c = 0; c < 3; c++) {
        int v = (i < NN) ? g_cnt[c][i] : 0;
#pragma unroll
        for (int o = 16; o; o >>= 1) v += __shfl_xor_sync(0xFFFFFFFFu, v, o);
        if (lane == 0) ws[c][warp] = v;
    }
    __syncthreads();
    if (threadIdx.x == 0) {
#pragma unroll
        for (int c = 0; c < 3; c++) {
            int s = 0;
#pragma unroll
            for (int j = 0; j < 8; j++) s += ws[c][j];
            g_bsum3[c][blockIdx.x] = s;
        }
    }
}

// ---------------- scan pass B: scan block sums (3 channels) ----------------
__global__ void k_scanB() {
    __shared__ int sh[256];
    int t = threadIdx.x;
    for (int c = 0; c < 3; c++) {
        int v = (t < NBLK) ? g_bsum3[c][t] : 0;
        sh[t] = v;
        __syncthreads();
        for (int d = 1; d < 256; d <<= 1) {
            int u = (t >= d) ? sh[t - d] : 0;
            __syncthreads();
            sh[t] += u;
            __syncthreads();
        }
        if (t < NBLK) g_bpre3[c][t] = sh[t] - v;
        if (t == NBLK - 1) g_off3[c][NN] = sh[t];
        __syncthreads();
    }
}

// ---------------- scan pass C: local scan + prefix + dinv (3 ch) ----------
__global__ void k_scanC() {
    int i = blockIdx.x * 256 + threadIdx.x;
    int lane = threadIdx.x & 31, warp = threadIdx.x >> 5;
    __shared__ int ws[8];
    for (int c = 0; c < 3; c++) {
        int v = (i < NN) ? g_cnt[c][i] : 0;
        int incl = v;
#pragma unroll
        for (int o = 1; o < 32; o <<= 1) {
            int t = __shfl_up_sync(0xFFFFFFFFu, incl, o);
            if (lane >= o) incl += t;
        }
        if (lane == 31) ws[warp] = incl;
        __syncthreads();
        if (warp == 0 && lane < 8) {
            int s = ws[lane];
            int si = s;
#pragma unroll
            for (int o = 1; o < 8; o <<= 1) {
                int t = __shfl_up_sync(0xFFu, si, o);
                if (lane >= o) si += t;
            }
            ws[lane] = si - s;
        }
        __syncthreads();
        if (i < NN) {
            int excl = (incl - v) + ws[warp] + g_bpre3[c][blockIdx.x];
            g_off3[c][i] = excl;
            g_cur3[c][i] = excl;
            g_dinv[c][i] = rsqrtf((float)(v + 1));
        }
        __syncthreads();
    }
}

// ---------------- CSR scatter: per-layer u16 src lists ----------------
__global__ void k_scatter(const int* __restrict__ ei,
                          const int* __restrict__ em) {
    int e = blockIdx.x * blockDim.x + threadIdx.x;
    if (e >= NE) return;
    int s = ei[e];
    int d = ei[NE + e];
    int m = em[e];
    int p0 = atomicAdd(&g_cur3[0][d], 1);
    g_csr16[0][p0] = (unsigned short)s;
    if (m == 1) {
        int p = atomicAdd(&g_cur3[1][d], 1);
        g_csr16[1][p] = (unsigned short)s;
    } else if (m == 2) {
        int p = atomicAdd(&g_cur3[2][d], 1);
        g_csr16[2][p] = (unsigned short)s;
    }
}

// ---------------- tensor-core GEMM via mma.sync tf32 (split hi/lo) ----------
// block 64x128, 8 warps (2x4), warp tile 32x32, K-tile 16,
// register-prefetch pipeline: next tile's LDGs overlap current tile's MMAs.
#define MMA_TF32(d, a, b)                                                     \
    asm volatile("mma.sync.aligned.m16n8k8.row.col.f32.tf32.tf32.f32 "        \
        "{%0,%1,%2,%3}, {%4,%5,%6,%7}, {%8,%9}, {%0,%1,%2,%3};"               \
        : "+f"((d)[0]), "+f"((d)[1]), "+f"((d)[2]), "+f"((d)[3])              \
        : "r"((a)[0]), "r"((a)[1]), "r"((a)[2]), "r"((a)[3]),                 \
          "r"((b)[0]), "r"((b)[1]))

__global__ void __launch_bounds__(256, 1)
k_gemm_mma(int inSel, const float* __restrict__ Xext, int wsel) {
    __shared__ unsigned Xh[64][20], Xl[64][20];       // X tile hi/lo, K-tile 16
    __shared__ unsigned Whs[16][136], Wls[16][136];   // W tile hi/lo (pad 136)
    const float* X = (inSel < 0) ? Xext : g_h[inSel];
    const unsigned* __restrict__ Wh = g_Wh32[wsel];
    const unsigned* __restrict__ Wl = g_Wl32[wsel];

    int tid  = threadIdx.x;
    int lane = tid & 31;
    int wid  = tid >> 5;
    int wRow = (wid & 1) * 32;
    int wCol = (wid >> 1) * 32;
    int rowBase = blockIdx.x * 64;

    int lr = lane >> 2;
    int lc = lane & 3;

    // prefetch addressing
    int xrow = tid >> 2, xkq = (tid & 3) * 4;
    int grow = rowBase + xrow;
    bool xvalid = grow < NN;
    int wkr0 = tid >> 5, wn0 = (tid & 31) * 4;   // j = tid
    int wkr1 = wkr0 + 8;                         // j = tid + 256, same n

    float acc[2][4][4];
#pragma unroll
    for (int a = 0; a < 2; a++)
#pragma unroll
        for (int b = 0; b < 4; b++)
#pragma unroll
            for (int c = 0; c < 4; c++) acc[a][b][c] = 0.f;

    float4 xv = make_float4(0.f, 0.f, 0.f, 0.f);
    uint4 wh0, wh1, wl0, wl1;
    // prefetch tile 0
    if (xvalid) xv = *(const float4*)&X[(size_t)grow * HID + xkq];
    wh0 = *(const uint4*)&Wh[wkr0 * HID + wn0];
    wh1 = *(const uint4*)&Wh[wkr1 * HID + wn0];
    wl0 = *(const uint4*)&Wl[wkr0 * HID + wn0];
    wl1 = *(const uint4*)&Wl[wkr1 * HID + wn0];

    for (int t = 0; t < 8; t++) {
        // stage prefetched tile into smem
        {
            unsigned h0 = to_tf32(xv.x), h1 = to_tf32(xv.y),
                     h2 = to_tf32(xv.z), h3 = to_tf32(xv.w);
            *(uint4*)&Xh[xrow][xkq] = make_uint4(h0, h1, h2, h3);
            *(uint4*)&Xl[xrow][xkq] =
                make_uint4(to_tf32(xv.x - __uint_as_float(h0)),
                           to_tf32(xv.y - __uint_as_float(h1)),
                           to_tf32(xv.z - __uint_as_float(h2)),
                           to_tf32(xv.w - __uint_as_float(h3)));
            *(uint4*)&Whs[wkr0][wn0] = wh0;
            *(uint4*)&Whs[wkr1][wn0] = wh1;
            *(uint4*)&Wls[wkr0][wn0] = wl0;
            *(uint4*)&Wls[wkr1][wn0] = wl1;
        }
        __syncthreads();

        // prefetch next tile (LDG latency overlaps compute below)
        if (t < 7) {
            int kt = (t + 1) * 16;
            if (xvalid) xv = *(const float4*)&X[(size_t)grow * HID + kt + xkq];
            wh0 = *(const uint4*)&Wh[(kt + wkr0) * HID + wn0];
            wh1 = *(const uint4*)&Wh[(kt + wkr1) * HID + wn0];
            wl0 = *(const uint4*)&Wl[(kt + wkr0) * HID + wn0];
            wl1 = *(const uint4*)&Wl[(kt + wkr1) * HID + wn0];
        }

#pragma unroll
        for (int ks = 0; ks < 16; ks += 8) {
            unsigned bh[4][2], bl[4][2];
#pragma unroll
            for (int tc = 0; tc < 4; tc++) {
                int n = wCol + tc * 8 + lr;
                bh[tc][0] = Whs[ks + lc][n];
                bh[tc][1] = Whs[ks + lc + 4][n];
                bl[tc][0] = Wls[ks + lc][n];
                bl[tc][1] = Wls[ks + lc + 4][n];
            }
#pragma unroll
            for (int tr = 0; tr < 2; tr++) {
                int r = wRow + tr * 16 + lr;
                unsigned ah[4], al[4];
                ah[0] = Xh[r][ks + lc];       ah[1] = Xh[r + 8][ks + lc];
                ah[2] = Xh[r][ks + lc + 4];   ah[3] = Xh[r + 8][ks + lc + 4];
                al[0] = Xl[r][ks + lc];       al[1] = Xl[r + 8][ks + lc];
                al[2] = Xl[r][ks + lc + 4];   al[3] = Xl[r + 8][ks + lc + 4];
#pragma unroll
                for (int tc = 0; tc < 4; tc++) {
                    MMA_TF32(acc[tr][tc], ah, bh[tc]);
                    MMA_TF32(acc[tr][tc], al, bh[tc]);
                    MMA_TF32(acc[tr][tc], ah, bl[tc]);
                }
            }
        }
        __syncthreads();
    }

    // epilogue
#pragma unroll
    for (int tr = 0; tr < 2; tr++) {
        int r0 = rowBase + wRow + tr * 16 + lr;
#pragma unroll
        for (int tc = 0; tc < 4; tc++) {
            int col = wCol + tc * 8 + 2 * lc;
            if (r0 < NN)
                *(float2*)&g_h[0][(size_t)r0 * HID + col] =
                    make_float2(acc[tr][tc][0], acc[tr][tc][1]);
            if (r0 + 8 < NN)
                *(float2*)&g_h[0][(size_t)(r0 + 8) * HID + col] =
                    make_float2(acc[tr][tc][2], acc[tr][tc][3]);
        }
    }
}

// ---------------- aggregation: warp per node, per-layer CSR ----------------
__global__ void k_agg(int layer, int outSel,
                      const float* __restrict__ bias,
                      int do_relu,
                      int doPool, const int* __restrict__ batch) {
    int wi = (blockIdx.x * blockDim.x + threadIdx.x) >> 5;
    if (wi >= NN) return;
    int lane = threadIdx.x & 31;

    const unsigned short* __restrict__ csr = g_csr16[layer];
    const int* __restrict__ off = g_off3[layer];
    const float* __restrict__ dinv = g_dinv[layer];

    float di = dinv[wi];
    int e0 = off[wi], e1 = off[wi + 1];

    float ax = 0.f, ay = 0.f, az = 0.f, aw = 0.f;
    int e = e0;
    for (; e + 2 <= e1; e += 2) {
        int s0 = csr[e], s1 = csr[e + 1];
        float c0 = di * dinv[s0];
        float c1 = di * dinv[s1];
        float4 h0 = *(const float4*)&g_h[0][(size_t)s0 * HID + lane * 4];
        float4 h1 = *(const float4*)&g_h[0][(size_t)s1 * HID + lane * 4];
        ax += c0 * h0.x + c1 * h1.x;
        ay += c0 * h0.y + c1 * h1.y;
        az += c0 * h0.z + c1 * h1.z;
        aw += c0 * h0.w + c1 * h1.w;
    }
    if (e < e1) {
        int s = csr[e];
        float c = di * dinv[s];
        float4 hv = *(const float4*)&g_h[0][(size_t)s * HID + lane * 4];
        ax += c * hv.x; ay += c * hv.y; az += c * hv.z; aw += c * hv.w;
    }
    float4 hs = *(const float4*)&g_h[0][(size_t)wi * HID + lane * 4];
    float c2 = di * di;
    ax += c2 * hs.x; ay += c2 * hs.y; az += c2 * hs.z; aw += c2 * hs.w;

    float4 bv = *(const float4*)&bias[lane * 4];
    ax += bv.x; ay += bv.y; az += bv.z; aw += bv.w;

    if (do_relu) {
        ax = fmaxf(ax, 0.f); ay = fmaxf(ay, 0.f);
        az = fmaxf(az, 0.f); aw = fmaxf(aw, 0.f);
    }
    float4 o; o.x = ax; o.y = ay; o.z = az; o.w = aw;
    *(float4*)&g_h[outSel][(size_t)wi * HID + lane * 4] = o;

    if (doPool) {
        int g = batch[wi];
        float* base = &g_pool[g * HID + lane * 4];
        atomicAdd(base + 0, ax);
        atomicAdd(base + 1, ay);
        atomicAdd(base + 2, az);
        atomicAdd(base + 3, aw);
        if (lane == 0) atomicAdd(&g_pcnt[g], 1.0f);
    }
}

// ---------------- head ----------------
__global__ void k_final(const float* __restrict__ Wl,
                        const float* __restrict__ bl,
                        float* __restrict__ out) {
    int g = blockIdx.x;
    int lane = threadIdx.x;
    float inv = 1.0f / fmaxf(g_pcnt[g], 1.0f);
    float s = 0.f;
    for (int j = lane; j < HID; j += 32)
        s += g_pool[g * HID + j] * inv * Wl[j];
#pragma unroll
    for (int o = 16; o; o >>= 1) s += __shfl_xor_sync(0xFFFFFFFFu, s, o);
    if (lane == 0) out[g] = s + bl[0];
}

// ---------------- launcher: kernel launches ONLY ----------------
extern "C" void kernel_launch(void* const* d_in, const int* in_sizes, int n_in,
                              void* d_out, int out_size) {
    const float* x     = (const float*)d_in[0];
    const int*   ei    = (const int*)d_in[1];
    const int*   em    = (const int*)d_in[2];
    const int*   batch = (const int*)d_in[3];
    const float* W1 = (const float*)d_in[4];
    const float* b1 = (const float*)d_in[5];
    const float* W2 = (const float*)d_in[6];
    const float* b2 = (const float*)d_in[7];
    const float* W3 = (const float*)d_in[8];
    const float* b3 = (const float*)d_in[9];
    const float* Wl = (const float*)d_in[10];
    const float* bl = (const float*)d_in[11];
    float* out = (float*)d_out;

    const int tb  = 256;
    const int gbN = (NN + tb - 1) / tb;
    const int gbE = (NE + tb - 1) / tb;
    const int gbW = (NN * 32 + tb - 1) / tb;

    k_zero   <<<gbN, tb>>>();
    k_prepW  <<<192, 256>>>(W1, W2, W3);
    k_hist   <<<gbE, tb>>>(ei, em);
    // GEMM1 at launch #4 for ncu
    k_gemm_mma<<<GEMM_CTAS, 256>>>(-1, x, 0);
    k_scanA  <<<NBLK, 256>>>();
    k_scanB  <<<1, 256>>>();
    k_scanC  <<<NBLK, 256>>>();
    k_scatter<<<gbE, tb>>>(ei, em);

    // layer 1: g_h[0] -> g_h[1] (relu)
    k_agg <<<gbW, tb>>>(0, 1, b1, 1, 0, batch);
    // layer 2
    k_gemm_mma<<<GEMM_CTAS, 256>>>(1, x, 1);
    k_agg <<<gbW, tb>>>(1, 2, b2, 1, 0, batch);
    // layer 3 + fused pool
    k_gemm_mma<<<GEMM_CTAS, 256>>>(2, x, 2);
    k_agg <<<gbW, tb>>>(2, 1, b3, 0, 1, batch);

    k_final<<<NG, 32>>>(Wl, bl, out);
}

// round 14
// speedup vs baseline: 1.0387x; 1.0387x over previous
#include <cuda_runtime.h>

#define NN 50000
#define NE 600000
#define HID 128
#define NG 64
#define NBLK 196        // ceil(50000/256)
#define GEMM_CTAS 782   // ceil(50000/64)

// ---- device scratch (no allocations allowed) ----
__device__ int   g_cnt[3][NN];
__device__ float g_dinv[3][NN];
__device__ int   g_off[NN + 1];
__device__ int   g_cur[NN];
__device__ int   g_bsum[NBLK];
__device__ int   g_bpre[NBLK];
__device__ unsigned g_csr[NE];
__device__ __align__(16) float g_h[3][NN * HID];
__device__ __align__(16) float g_pool[NG * HID];
__device__ float g_pcnt[NG];
// tf32 hi/lo bit-pattern images of W, row-major [k][n]
__device__ __align__(16) unsigned g_Wh32[3][HID * HID];
__device__ __align__(16) unsigned g_Wl32[3][HID * HID];

__device__ __forceinline__ unsigned to_tf32(float v) {
    unsigned u;
    asm("cvt.rna.tf32.f32 %0, %1;" : "=r"(u) : "f"(v));
    return u;
}

// ---------------- init ----------------
__global__ void k_zero() {
    int i = blockIdx.x * blockDim.x + threadIdx.x;
    if (i < NN) { g_cnt[0][i] = 0; g_cnt[1][i] = 0; g_cnt[2][i] = 0; }
    if (i < NG * HID) g_pool[i] = 0.0f;
    if (i < NG) g_pcnt[i] = 0.0f;
}

// ---------------- W prep: f32 -> tf32 hi/lo bit images ----------------
__global__ void k_prepW(const float* __restrict__ W1,
                        const float* __restrict__ W2,
                        const float* __restrict__ W3) {
    int sel = blockIdx.x >> 6;
    int idx = (blockIdx.x & 63) * 256 + threadIdx.x;   // 0..16383
    const float* W = sel == 0 ? W1 : (sel == 1 ? W2 : W3);
    float v = W[idx];
    unsigned uh = to_tf32(v);
    float lo = v - __uint_as_float(uh);
    g_Wh32[sel][idx] = uh;
    g_Wl32[sel][idx] = to_tf32(lo);
}

// ---------------- degree histogram ----------------
__global__ void k_hist(const int* __restrict__ ei,
                       const int* __restrict__ em) {
    int e = blockIdx.x * blockDim.x + threadIdx.x;
    if (e >= NE) return;
    int d = ei[NE + e];
    int m = em[e];
    atomicAdd(&g_cnt[0][d], 1);
    if (m == 1) atomicAdd(&g_cnt[1][d], 1);
    else if (m == 2) atomicAdd(&g_cnt[2][d], 1);
}

// ---------------- scan passes (single channel: total degree) ------------
__global__ void k_scanA() {
    int i = blockIdx.x * 256 + threadIdx.x;
    int lane = threadIdx.x & 31, warp = threadIdx.x >> 5;
    int v = (i < NN) ? g_cnt[0][i] : 0;
#pragma unroll
    for (int o = 16; o; o >>= 1) v += __shfl_xor_sync(0xFFFFFFFFu, v, o);
    __shared__ int ws[8];
    if (lane == 0) ws[warp] = v;
    __syncthreads();
    if (threadIdx.x == 0) {
        int s = 0;
#pragma unroll
        for (int j = 0; j < 8; j++) s += ws[j];
        g_bsum[blockIdx.x] = s;
    }
}

__global__ void k_scanB() {
    __shared__ int sh[256];
    int t = threadIdx.x;
    int v = (t < NBLK) ? g_bsum[t] : 0;
    sh[t] = v;
    __syncthreads();
    for (int d = 1; d < 256; d <<= 1) {
        int u = (t >= d) ? sh[t - d] : 0;
        __syncthreads();
        sh[t] += u;
        __syncthreads();
    }
    if (t < NBLK) g_bpre[t] = sh[t] - v;
    if (t == NBLK - 1) g_off[NN] = sh[t];
}

__global__ void k_scanC() {
    int i = blockIdx.x * 256 + threadIdx.x;
    int lane = threadIdx.x & 31, warp = threadIdx.x >> 5;
    int v = (i < NN) ? g_cnt[0][i] : 0;
    int incl = v;
#pragma unroll
    for (int o = 1; o < 32; o <<= 1) {
        int t = __shfl_up_sync(0xFFFFFFFFu, incl, o);
        if (lane >= o) incl += t;
    }
    __shared__ int ws[8];
    if (lane == 31) ws[warp] = incl;
    __syncthreads();
    if (warp == 0 && lane < 8) {
        int s = ws[lane];
        int si = s;
#pragma unroll
        for (int o = 1; o < 8; o <<= 1) {
            int t = __shfl_up_sync(0xFFu, si, o);
            if (lane >= o) si += t;
        }
        ws[lane] = si - s;
    }
    __syncthreads();
    if (i < NN) {
        int excl = (incl - v) + ws[warp] + g_bpre[blockIdx.x];
        g_off[i] = excl;
        g_cur[i] = excl;
        g_dinv[0][i] = rsqrtf((float)(v + 1));
        g_dinv[1][i] = rsqrtf((float)(g_cnt[1][i] + 1));
        g_dinv[2][i] = rsqrtf((float)(g_cnt[2][i] + 1));
    }
}

// ---------------- CSR scatter (src | mask<<16, single list) ------------
__global__ void k_scatter(const int* __restrict__ ei,
                          const int* __restrict__ em) {
    int e = blockIdx.x * blockDim.x + threadIdx.x;
    if (e >= NE) return;
    int s = ei[e];
    int d = ei[NE + e];
    int m = em[e];
    int pos = atomicAdd(&g_cur[d], 1);
    g_csr[pos] = (unsigned)s | ((unsigned)m << 16);   // s < 50000 < 2^16
}

// ---------------- tensor-core GEMM via mma.sync tf32 (split hi/lo) ----------
// block 64x128, 8 warps (2x4), warp tile 32x32, K-tile 16,
// register-prefetch pipeline: next tile's LDGs overlap current tile's MMAs.
#define MMA_TF32(d, a, b)                                                     \
    asm volatile("mma.sync.aligned.m16n8k8.row.col.f32.tf32.tf32.f32 "        \
        "{%0,%1,%2,%3}, {%4,%5,%6,%7}, {%8,%9}, {%0,%1,%2,%3};"               \
        : "+f"((d)[0]), "+f"((d)[1]), "+f"((d)[2]), "+f"((d)[3])              \
        : "r"((a)[0]), "r"((a)[1]), "r"((a)[2]), "r"((a)[3]),                 \
          "r"((b)[0]), "r"((b)[1]))

__global__ void __launch_bounds__(256, 1)
k_gemm_mma(int inSel, const float* __restrict__ Xext, int wsel) {
    __shared__ unsigned Xh[64][20], Xl[64][20];       // X tile hi/lo, K-tile 16
    __shared__ unsigned Whs[16][136], Wls[16][136];   // W tile hi/lo (pad 136)
    const float* X = (inSel < 0) ? Xext : g_h[inSel];
    const unsigned* __restrict__ Wh = g_Wh32[wsel];
    const unsigned* __restrict__ Wl = g_Wl32[wsel];

    int tid  = threadIdx.x;
    int lane = tid & 31;
    int wid  = tid >> 5;
    int wRow = (wid & 1) * 32;
    int wCol = (wid >> 1) * 32;
    int rowBase = blockIdx.x * 64;

    int lr = lane >> 2;
    int lc = lane & 3;

    // prefetch addressing
    int xrow = tid >> 2, xkq = (tid & 3) * 4;
    int grow = rowBase + xrow;
    bool xvalid = grow < NN;
    int wkr0 = tid >> 5, wn0 = (tid & 31) * 4;   // j = tid
    int wkr1 = wkr0 + 8;                         // j = tid + 256, same n

    float acc[2][4][4];
#pragma unroll
    for (int a = 0; a < 2; a++)
#pragma unroll
        for (int b = 0; b < 4; b++)
#pragma unroll
            for (int c = 0; c < 4; c++) acc[a][b][c] = 0.f;

    float4 xv = make_float4(0.f, 0.f, 0.f, 0.f);
    uint4 wh0, wh1, wl0, wl1;
    // prefetch tile 0
    if (xvalid) xv = *(const float4*)&X[(size_t)grow * HID + xkq];
    wh0 = *(const uint4*)&Wh[wkr0 * HID + wn0];
    wh1 = *(const uint4*)&Wh[wkr1 * HID + wn0];
    wl0 = *(const uint4*)&Wl[wkr0 * HID + wn0];
    wl1 = *(const uint4*)&Wl[wkr1 * HID + wn0];

    for (int t = 0; t < 8; t++) {
        // stage prefetched tile into smem
        {
            unsigned h0 = to_tf32(xv.x), h1 = to_tf32(xv.y),
                     h2 = to_tf32(xv.z), h3 = to_tf32(xv.w);
            *(uint4*)&Xh[xrow][xkq] = make_uint4(h0, h1, h2, h3);
            *(uint4*)&Xl[xrow][xkq] =
                make_uint4(to_tf32(xv.x - __uint_as_float(h0)),
                           to_tf32(xv.y - __uint_as_float(h1)),
                           to_tf32(xv.z - __uint_as_float(h2)),
                           to_tf32(xv.w - __uint_as_float(h3)));
            *(uint4*)&Whs[wkr0][wn0] = wh0;
            *(uint4*)&Whs[wkr1][wn0] = wh1;
            *(uint4*)&Wls[wkr0][wn0] = wl0;
            *(uint4*)&Wls[wkr1][wn0] = wl1;
        }
        __syncthreads();

        // prefetch next tile (LDG latency overlaps compute below)
        if (t < 7) {
            int kt = (t + 1) * 16;
            if (xvalid) xv = *(const float4*)&X[(size_t)grow * HID + kt + xkq];
            wh0 = *(const uint4*)&Wh[(kt + wkr0) * HID + wn0];
            wh1 = *(const uint4*)&Wh[(kt + wkr1) * HID + wn0];
            wl0 = *(const uint4*)&Wl[(kt + wkr0) * HID + wn0];
            wl1 = *(const uint4*)&Wl[(kt + wkr1) * HID + wn0];
        }

#pragma unroll
        for (int ks = 0; ks < 16; ks += 8) {
            unsigned bh[4][2], bl[4][2];
#pragma unroll
            for (int tc = 0; tc < 4; tc++) {
                int n = wCol + tc * 8 + lr;
                bh[tc][0] = Whs[ks + lc][n];
                bh[tc][1] = Whs[ks + lc + 4][n];
                bl[tc][0] = Wls[ks + lc][n];
                bl[tc][1] = Wls[ks + lc + 4][n];
            }
#pragma unroll
            for (int tr = 0; tr < 2; tr++) {
                int r = wRow + tr * 16 + lr;
                unsigned ah[4], al[4];
                ah[0] = Xh[r][ks + lc];       ah[1] = Xh[r + 8][ks + lc];
                ah[2] = Xh[r][ks + lc + 4];   ah[3] = Xh[r + 8][ks + lc + 4];
                al[0] = Xl[r][ks + lc];       al[1] = Xl[r + 8][ks + lc];
                al[2] = Xl[r][ks + lc + 4];   al[3] = Xl[r + 8][ks + lc + 4];
#pragma unroll
                for (int tc = 0; tc < 4; tc++) {
                    MMA_TF32(acc[tr][tc], ah, bh[tc]);
                    MMA_TF32(acc[tr][tc], al, bh[tc]);
                    MMA_TF32(acc[tr][tc], ah, bl[tc]);
                }
            }
        }
        __syncthreads();
    }

    // epilogue
#pragma unroll
    for (int tr = 0; tr < 2; tr++) {
        int r0 = rowBase + wRow + tr * 16 + lr;
#pragma unroll
        for (int tc = 0; tc < 4; tc++) {
            int col = wCol + tc * 8 + 2 * lc;
            if (r0 < NN)
                *(float2*)&g_h[0][(size_t)r0 * HID + col] =
                    make_float2(acc[tr][tc][0], acc[tr][tc][1]);
            if (r0 + 8 < NN)
                *(float2*)&g_h[0][(size_t)(r0 + 8) * HID + col] =
                    make_float2(acc[tr][tc][2], acc[tr][tc][3]);
        }
    }
}

// ---------------- aggregation: warp per node, packed CSR ----------------
__global__ void k_agg(int layer, int outSel,
                      const float* __restrict__ bias,
                      int mode, int do_relu,
                      int doPool, const int* __restrict__ batch) {
    int wi = (blockIdx.x * blockDim.x + threadIdx.x) >> 5;
    if (wi >= NN) return;
    int lane = threadIdx.x & 31;

    const float* __restrict__ dinv = g_dinv[layer];
    float di = dinv[wi];
    int e0 = g_off[wi], e1 = g_off[wi + 1];

    float ax = 0.f, ay = 0.f, az = 0.f, aw = 0.f;
    int e = e0;
    for (; e + 2 <= e1; e += 2) {
        unsigned p0 = g_csr[e], p1 = g_csr[e + 1];
        int s0 = (int)(p0 & 0xFFFFu), s1 = (int)(p1 & 0xFFFFu);
        bool k0 = (mode == 0) | ((int)(p0 >> 16) == mode);
        bool k1 = (mode == 0) | ((int)(p1 >> 16) == mode);
        float c0 = k0 ? di * dinv[s0] : 0.f;
        float c1 = k1 ? di * dinv[s1] : 0.f;
        float4 h0 = *(const float4*)&g_h[0][(size_t)s0 * HID + lane * 4];
        float4 h1 = *(const float4*)&g_h[0][(size_t)s1 * HID + lane * 4];
        ax += c0 * h0.x + c1 * h1.x;
        ay += c0 * h0.y + c1 * h1.y;
        az += c0 * h0.z + c1 * h1.z;
        aw += c0 * h0.w + c1 * h1.w;
    }
    if (e < e1) {
        unsigned p = g_csr[e];
        int s = (int)(p & 0xFFFFu);
        if (mode == 0 || (int)(p >> 16) == mode) {
            float c = di * dinv[s];
            float4 hv = *(const float4*)&g_h[0][(size_t)s * HID + lane * 4];
            ax += c * hv.x; ay += c * hv.y; az += c * hv.z; aw += c * hv.w;
        }
    }
    float4 hs = *(const float4*)&g_h[0][(size_t)wi * HID + lane * 4];
    float c2 = di * di;
    ax += c2 * hs.x; ay += c2 * hs.y; az += c2 * hs.z; aw += c2 * hs.w;

    float4 bv = *(const float4*)&bias[lane * 4];
    ax += bv.x; ay += bv.y; az += bv.z; aw += bv.w;

    if (do_relu) {
        ax = fmaxf(ax, 0.f); ay = fmaxf(ay, 0.f);
        az = fmaxf(az, 0.f); aw = fmaxf(aw, 0.f);
    }
    float4 o; o.x = ax; o.y = ay; o.z = az; o.w = aw;
    *(float4*)&g_h[outSel][(size_t)wi * HID + lane * 4] = o;

    if (doPool) {
        int g = batch[wi];
        float* base = &g_pool[g * HID + lane * 4];
        atomicAdd(base + 0, ax);
        atomicAdd(base + 1, ay);
        atomicAdd(base + 2, az);
        atomicAdd(base + 3, aw);
        if (lane == 0) atomicAdd(&g_pcnt[g], 1.0f);
    }
}

// ---------------- head ----------------
__global__ void k_final(const float* __restrict__ Wl,
                        const float* __restrict__ bl,
                        float* __restrict__ out) {
    int g = blockIdx.x;
    int lane = threadIdx.x;
    float inv = 1.0f / fmaxf(g_pcnt[g], 1.0f);
    float s = 0.f;
    for (int j = lane; j < HID; j += 32)
        s += g_pool[g * HID + j] * inv * Wl[j];
#pragma unroll
    for (int o = 16; o; o >>= 1) s += __shfl_xor_sync(0xFFFFFFFFu, s, o);
    if (lane == 0) out[g] = s + bl[0];
}

// ---------------- launcher: kernel launches ONLY ----------------
extern "C" void kernel_launch(void* const* d_in, const int* in_sizes, int n_in,
                              void* d_out, int out_size) {
    const float* x     = (const float*)d_in[0];
    const int*   ei    = (const int*)d_in[1];
    const int*   em    = (const int*)d_in[2];
    const int*   batch = (const int*)d_in[3];
    const float* W1 = (const float*)d_in[4];
    const float* b1 = (const float*)d_in[5];
    const float* W2 = (const float*)d_in[6];
    const float* b2 = (const float*)d_in[7];
    const float* W3 = (const float*)d_in[8];
    const float* b3 = (const float*)d_in[9];
    const float* Wl = (const float*)d_in[10];
    const float* bl = (const float*)d_in[11];
    float* out = (float*)d_out;

    const int tb  = 256;
    const int gbN = (NN + tb - 1) / tb;
    const int gbE = (NE + tb - 1) / tb;
    const int gbW = (NN * 32 + tb - 1) / tb;

    k_zero   <<<gbN, tb>>>();
    k_prepW  <<<192, 256>>>(W1, W2, W3);
    k_hist   <<<gbE, tb>>>(ei, em);
    // GEMM1 at launch #4 for ncu
    k_gemm_mma<<<GEMM_CTAS, 256>>>(-1, x, 0);
    k_scanA  <<<NBLK, 256>>>();
    k_scanB  <<<1, 256>>>();
    k_scanC  <<<NBLK, 256>>>();
    k_scatter<<<gbE, tb>>>(ei, em);

    // layer 1: g_h[0] -> g_h[1] (relu, all edges)
    k_agg <<<gbW, tb>>>(0, 1, b1, 0, 1, 0, batch);
    // layer 2
    k_gemm_mma<<<GEMM_CTAS, 256>>>(1, x, 1);
    k_agg <<<gbW, tb>>>(1, 2, b2, 1, 1, 0, batch);
    // layer 3 + fused pool
    k_gemm_mma<<<GEMM_CTAS, 256>>>(2, x, 2);
    k_agg <<<gbW, tb>>>(2, 1, b3, 2, 0, 1, batch);

    k_final<<<NG, 32>>>(Wl, bl, out);
}

// round 15
// speedup vs baseline: 1.0742x; 1.0342x over previous
#include <cuda_runtime.h>

#define NN 50000
#define NE 600000
#define HID 128
#define NG 64
#define NBLK 196        // ceil(50000/256)
#define GEMM_CTAS 782   // ceil(50000/64)

// ---- device scratch (no allocations allowed) ----
__device__ int   g_cnt[3][NN];
__device__ float g_dinv[3][NN];
__device__ int   g_off[NN + 1];
__device__ int   g_cur[NN];
__device__ int   g_bsum[NBLK];
__device__ int   g_bpre[NBLK];
__device__ unsigned g_csr[NE];
__device__ __align__(16) float g_h[3][NN * HID];
__device__ __align__(16) float g_pool[NG * HID];
__device__ float g_pcnt[NG];
// tf32 hi/lo bit-pattern images of W, row-major [k][n]
__device__ __align__(16) unsigned g_Wh32[3][HID * HID];
__device__ __align__(16) unsigned g_Wl32[3][HID * HID];

__device__ __forceinline__ unsigned to_tf32(float v) {
    unsigned u;
    asm("cvt.rna.tf32.f32 %0, %1;" : "=r"(u) : "f"(v));
    return u;
}

// ---------------- init ----------------
__global__ void k_zero() {
    int i = blockIdx.x * blockDim.x + threadIdx.x;
    if (i < NN) { g_cnt[0][i] = 0; g_cnt[1][i] = 0; g_cnt[2][i] = 0; }
    if (i < NG * HID) g_pool[i] = 0.0f;
    if (i < NG) g_pcnt[i] = 0.0f;
}

// ---------------- W prep: f32 -> tf32 hi/lo bit images ----------------
__global__ void k_prepW(const float* __restrict__ W1,
                        const float* __restrict__ W2,
                        const float* __restrict__ W3) {
    int sel = blockIdx.x >> 6;
    int idx = (blockIdx.x & 63) * 256 + threadIdx.x;   // 0..16383
    const float* W = sel == 0 ? W1 : (sel == 1 ? W2 : W3);
    float v = W[idx];
    unsigned uh = to_tf32(v);
    float lo = v - __uint_as_float(uh);
    g_Wh32[sel][idx] = uh;
    g_Wl32[sel][idx] = to_tf32(lo);
}

// ---------------- degree histogram ----------------
__global__ void k_hist(const int* __restrict__ ei,
                       const int* __restrict__ em) {
    int e = blockIdx.x * blockDim.x + threadIdx.x;
    if (e >= NE) return;
    int d = ei[NE + e];
    int m = em[e];
    atomicAdd(&g_cnt[0][d], 1);
    if (m == 1) atomicAdd(&g_cnt[1][d], 1);
    else if (m == 2) atomicAdd(&g_cnt[2][d], 1);
}

// ---------------- scan passes (single channel: total degree) ------------
__global__ void k_scanA() {
    int i = blockIdx.x * 256 + threadIdx.x;
    int lane = threadIdx.x & 31, warp = threadIdx.x >> 5;
    int v = (i < NN) ? g_cnt[0][i] : 0;
#pragma unroll
    for (int o = 16; o; o >>= 1) v += __shfl_xor_sync(0xFFFFFFFFu, v, o);
    __shared__ int ws[8];
    if (lane == 0) ws[warp] = v;
    __syncthreads();
    if (threadIdx.x == 0) {
        int s = 0;
#pragma unroll
        for (int j = 0; j < 8; j++) s += ws[j];
        g_bsum[blockIdx.x] = s;
    }
}

__global__ void k_scanB() {
    __shared__ int sh[256];
    int t = threadIdx.x;
    int v = (t < NBLK) ? g_bsum[t] : 0;
    sh[t] = v;
    __syncthreads();
    for (int d = 1; d < 256; d <<= 1) {
        int u = (t >= d) ? sh[t - d] : 0;
        __syncthreads();
        sh[t] += u;
        __syncthreads();
    }
    if (t < NBLK) g_bpre[t] = sh[t] - v;
    if (t == NBLK - 1) g_off[NN] = sh[t];
}

__global__ void k_scanC() {
    int i = blockIdx.x * 256 + threadIdx.x;
    int lane = threadIdx.x & 31, warp = threadIdx.x >> 5;
    int v = (i < NN) ? g_cnt[0][i] : 0;
    int incl = v;
#pragma unroll
    for (int o = 1; o < 32; o <<= 1) {
        int t = __shfl_up_sync(0xFFFFFFFFu, incl, o);
        if (lane >= o) incl += t;
    }
    __shared__ int ws[8];
    if (lane == 31) ws[warp] = incl;
    __syncthreads();
    if (warp == 0 && lane < 8) {
        int s = ws[lane];
        int si = s;
#pragma unroll
        for (int o = 1; o < 8; o <<= 1) {
            int t = __shfl_up_sync(0xFFu, si, o);
            if (lane >= o) si += t;
        }
        ws[lane] = si - s;
    }
    __syncthreads();
    if (i < NN) {
        int excl = (incl - v) + ws[warp] + g_bpre[blockIdx.x];
        g_off[i] = excl;
        g_cur[i] = excl;
        g_dinv[0][i] = rsqrtf((float)(v + 1));
        g_dinv[1][i] = rsqrtf((float)(g_cnt[1][i] + 1));
        g_dinv[2][i] = rsqrtf((float)(g_cnt[2][i] + 1));
    }
}

// ---------------- CSR scatter (src | mask<<16, single list) ------------
__global__ void k_scatter(const int* __restrict__ ei,
                          const int* __restrict__ em) {
    int e = blockIdx.x * blockDim.x + threadIdx.x;
    if (e >= NE) return;
    int s = ei[e];
    int d = ei[NE + e];
    int m = em[e];
    int pos = atomicAdd(&g_cur[d], 1);
    g_csr[pos] = (unsigned)s | ((unsigned)m << 16);   // s < 50000 < 2^16
}

// ---------------- tensor-core GEMM via mma.sync tf32 (split hi/lo) ----------
// block 64x128, 8 warps (2x4), warp tile 32x32, K-tile 16,
// register-prefetch pipeline: next tile's LDGs overlap current tile's MMAs.
#define MMA_TF32(d, a, b)                                                     \
    asm volatile("mma.sync.aligned.m16n8k8.row.col.f32.tf32.tf32.f32 "        \
        "{%0,%1,%2,%3}, {%4,%5,%6,%7}, {%8,%9}, {%0,%1,%2,%3};"               \
        : "+f"((d)[0]), "+f"((d)[1]), "+f"((d)[2]), "+f"((d)[3])              \
        : "r"((a)[0]), "r"((a)[1]), "r"((a)[2]), "r"((a)[3]),                 \
          "r"((b)[0]), "r"((b)[1]))

__global__ void __launch_bounds__(256, 1)
k_gemm_mma(int inSel, const float* __restrict__ Xext, int wsel) {
    __shared__ unsigned Xh[64][20], Xl[64][20];       // X tile hi/lo, K-tile 16
    __shared__ unsigned Whs[16][136], Wls[16][136];   // W tile hi/lo (pad 136)
    const float* X = (inSel < 0) ? Xext : g_h[inSel];
    const unsigned* __restrict__ Wh = g_Wh32[wsel];
    const unsigned* __restrict__ Wl = g_Wl32[wsel];

    int tid  = threadIdx.x;
    int lane = tid & 31;
    int wid  = tid >> 5;
    int wRow = (wid & 1) * 32;
    int wCol = (wid >> 1) * 32;
    int rowBase = blockIdx.x * 64;

    int lr = lane >> 2;
    int lc = lane & 3;

    // prefetch addressing
    int xrow = tid >> 2, xkq = (tid & 3) * 4;
    int grow = rowBase + xrow;
    bool xvalid = grow < NN;
    int wkr0 = tid >> 5, wn0 = (tid & 31) * 4;   // j = tid
    int wkr1 = wkr0 + 8;                         // j = tid + 256, same n

    float acc[2][4][4];
#pragma unroll
    for (int a = 0; a < 2; a++)
#pragma unroll
        for (int b = 0; b < 4; b++)
#pragma unroll
            for (int c = 0; c < 4; c++) acc[a][b][c] = 0.f;

    float4 xv = make_float4(0.f, 0.f, 0.f, 0.f);
    uint4 wh0, wh1, wl0, wl1;
    // prefetch tile 0
    if (xvalid) xv = *(const float4*)&X[(size_t)grow * HID + xkq];
    wh0 = *(const uint4*)&Wh[wkr0 * HID + wn0];
    wh1 = *(const uint4*)&Wh[wkr1 * HID + wn0];
    wl0 = *(const uint4*)&Wl[wkr0 * HID + wn0];
    wl1 = *(const uint4*)&Wl[wkr1 * HID + wn0];

    for (int t = 0; t < 8; t++) {
        // stage prefetched tile into smem
        {
            unsigned h0 = to_tf32(xv.x), h1 = to_tf32(xv.y),
                     h2 = to_tf32(xv.z), h3 = to_tf32(xv.w);
            *(uint4*)&Xh[xrow][xkq] = make_uint4(h0, h1, h2, h3);
            *(uint4*)&Xl[xrow][xkq] =
                make_uint4(to_tf32(xv.x - __uint_as_float(h0)),
                           to_tf32(xv.y - __uint_as_float(h1)),
                           to_tf32(xv.z - __uint_as_float(h2)),
                           to_tf32(xv.w - __uint_as_float(h3)));
            *(uint4*)&Whs[wkr0][wn0] = wh0;
            *(uint4*)&Whs[wkr1][wn0] = wh1;
            *(uint4*)&Wls[wkr0][wn0] = wl0;
            *(uint4*)&Wls[wkr1][wn0] = wl1;
        }
        __syncthreads();

        // prefetch next tile (LDG latency overlaps compute below)
        if (t < 7) {
            int kt = (t + 1) * 16;
            if (xvalid) xv = *(const float4*)&X[(size_t)grow * HID + kt + xkq];
            wh0 = *(const uint4*)&Wh[(kt + wkr0) * HID + wn0];
            wh1 = *(const uint4*)&Wh[(kt + wkr1) * HID + wn0];
            wl0 = *(const uint4*)&Wl[(kt + wkr0) * HID + wn0];
            wl1 = *(const uint4*)&Wl[(kt + wkr1) * HID + wn0];
        }

#pragma unroll
        for (int ks = 0; ks < 16; ks += 8) {
            unsigned bh[4][2], bl[4][2];
#pragma unroll
            for (int tc = 0; tc < 4; tc++) {
                int n = wCol + tc * 8 + lr;
                bh[tc][0] = Whs[ks + lc][n];
                bh[tc][1] = Whs[ks + lc + 4][n];
                bl[tc][0] = Wls[ks + lc][n];
                bl[tc][1] = Wls[ks + lc + 4][n];
            }
#pragma unroll
            for (int tr = 0; tr < 2; tr++) {
                int r = wRow + tr * 16 + lr;
                unsigned ah[4], al[4];
                ah[0] = Xh[r][ks + lc];       ah[1] = Xh[r + 8][ks + lc];
                ah[2] = Xh[r][ks + lc + 4];   ah[3] = Xh[r + 8][ks + lc + 4];
                al[0] = Xl[r][ks + lc];       al[1] = Xl[r + 8][ks + lc];
                al[2] = Xl[r][ks + lc + 4];   al[3] = Xl[r + 8][ks + lc + 4];
#pragma unroll
                for (int tc = 0; tc < 4; tc++) {
                    MMA_TF32(acc[tr][tc], ah, bh[tc]);
                    MMA_TF32(acc[tr][tc], al, bh[tc]);
                    MMA_TF32(acc[tr][tc], ah, bl[tc]);
                }
            }
        }
        __syncthreads();
    }

    // epilogue
#pragma unroll
    for (int tr = 0; tr < 2; tr++) {
        int r0 = rowBase + wRow + tr * 16 + lr;
#pragma unroll
        for (int tc = 0; tc < 4; tc++) {
            int col = wCol + tc * 8 + 2 * lc;
            if (r0 < NN)
                *(float2*)&g_h[0][(size_t)r0 * HID + col] =
                    make_float2(acc[tr][tc][0], acc[tr][tc][1]);
            if (r0 + 8 < NN)
                *(float2*)&g_h[0][(size_t)(r0 + 8) * HID + col] =
                    make_float2(acc[tr][tc][2], acc[tr][tc][3]);
        }
    }
}

// ---------------- aggregation: lane-parallel edge staging ----------------
// 32 lanes cooperatively load 32 CSR entries + dinv (coalesced), ballot the
// keep-mask, then iterate only surviving edges via ffs+shfl. Masked edges
// never issue their 512B h-load; h-load addresses known immediately -> MLP.
__global__ void k_agg(int layer, int outSel,
                      const float* __restrict__ bias,
                      int mode, int do_relu,
                      int doPool, const int* __restrict__ batch) {
    int wi = (blockIdx.x * blockDim.x + threadIdx.x) >> 5;
    if (wi >= NN) return;
    int lane = threadIdx.x & 31;

    const float* __restrict__ dinv = g_dinv[layer];
    float di = dinv[wi];
    int e0 = g_off[wi], e1 = g_off[wi + 1];

    float ax = 0.f, ay = 0.f, az = 0.f, aw = 0.f;
    for (int base = e0; base < e1; base += 32) {
        int idx = base + lane;
        bool valid = idx < e1;
        unsigned p = valid ? g_csr[idx] : 0u;
        int s = (int)(p & 0xFFFFu);
        bool keep = valid && (mode == 0 || (int)(p >> 16) == mode);
        float c = keep ? di * dinv[s] : 0.f;
        unsigned bal = __ballot_sync(0xFFFFFFFFu, keep);
        while (bal) {
            int j = __ffs(bal) - 1;
            bal &= bal - 1;
            float cj = __shfl_sync(0xFFFFFFFFu, c, j);
            int   sj = __shfl_sync(0xFFFFFFFFu, s, j);
            float4 hv = *(const float4*)&g_h[0][(size_t)sj * HID + lane * 4];
            ax += cj * hv.x; ay += cj * hv.y;
            az += cj * hv.z; aw += cj * hv.w;
        }
    }

    float4 hs = *(const float4*)&g_h[0][(size_t)wi * HID + lane * 4];
    float c2 = di * di;
    ax += c2 * hs.x; ay += c2 * hs.y; az += c2 * hs.z; aw += c2 * hs.w;

    float4 bv = *(const float4*)&bias[lane * 4];
    ax += bv.x; ay += bv.y; az += bv.z; aw += bv.w;

    if (do_relu) {
        ax = fmaxf(ax, 0.f); ay = fmaxf(ay, 0.f);
        az = fmaxf(az, 0.f); aw = fmaxf(aw, 0.f);
    }
    float4 o; o.x = ax; o.y = ay; o.z = az; o.w = aw;
    *(float4*)&g_h[outSel][(size_t)wi * HID + lane * 4] = o;

    if (doPool) {
        int g = batch[wi];
        float* base = &g_pool[g * HID + lane * 4];
        atomicAdd(base + 0, ax);
        atomicAdd(base + 1, ay);
        atomicAdd(base + 2, az);
        atomicAdd(base + 3, aw);
        if (lane == 0) atomicAdd(&g_pcnt[g], 1.0f);
    }
}

// ---------------- head ----------------
__global__ void k_final(const float* __restrict__ Wl,
                        const float* __restrict__ bl,
                        float* __restrict__ out) {
    int g = blockIdx.x;
    int lane = threadIdx.x;
    float inv = 1.0f / fmaxf(g_pcnt[g], 1.0f);
    float s = 0.f;
    for (int j = lane; j < HID; j += 32)
        s += g_pool[g * HID + j] * inv * Wl[j];
#pragma unroll
    for (int o = 16; o; o >>= 1) s += __shfl_xor_sync(0xFFFFFFFFu, s, o);
    if (lane == 0) out[g] = s + bl[0];
}

// ---------------- launcher: kernel launches ONLY ----------------
extern "C" void kernel_launch(void* const* d_in, const int* in_sizes, int n_in,
                              void* d_out, int out_size) {
    const float* x     = (const float*)d_in[0];
    const int*   ei    = (const int*)d_in[1];
    const int*   em    = (const int*)d_in[2];
    const int*   batch = (const int*)d_in[3];
    const float* W1 = (const float*)d_in[4];
    const float* b1 = (const float*)d_in[5];
    const float* W2 = (const float*)d_in[6];
    const float* b2 = (const float*)d_in[7];
    const float* W3 = (const float*)d_in[8];
    const float* b3 = (const float*)d_in[9];
    const float* Wl = (const float*)d_in[10];
    const float* bl = (const float*)d_in[11];
    float* out = (float*)d_out;

    const int tb  = 256;
    const int gbN = (NN + tb - 1) / tb;
    const int gbE = (NE + tb - 1) / tb;
    const int gbW = (NN * 32 + tb - 1) / tb;

    k_zero   <<<gbN, tb>>>();
    k_prepW  <<<192, 256>>>(W1, W2, W3);
    k_hist   <<<gbE, tb>>>(ei, em);
    // GEMM1 at launch #4 for ncu
    k_gemm_mma<<<GEMM_CTAS, 256>>>(-1, x, 0);
    k_scanA  <<<NBLK, 256>>>();
    k_scanB  <<<1, 256>>>();
    k_scanC  <<<NBLK, 256>>>();
    k_scatter<<<gbE, tb>>>(ei, em);

    // layer 1: g_h[0] -> g_h[1] (relu, all edges)
    k_agg <<<gbW, tb>>>(0, 1, b1, 0, 1, 0, batch);
    // layer 2
    k_gemm_mma<<<GEMM_CTAS, 256>>>(1, x, 1);
    k_agg <<<gbW, tb>>>(1, 2, b2, 1, 1, 0, batch);
    // layer 3 + fused pool
    k_gemm_mma<<<GEMM_CTAS, 256>>>(2, x, 2);
    k_agg <<<gbW, tb>>>(2, 1, b3, 2, 0, 1, batch);

    k_final<<<NG, 32>>>(Wl, bl, out);
}

// round 16
// speedup vs baseline: 1.0931x; 1.0176x over previous
#include <cuda_runtime.h>

#define NN 50000
#define NE 600000
#define HID 128
#define NG 64
#define NBLK 196        // ceil(50000/256)
#define GEMM_CTAS 782   // ceil(50000/64)

// ---- device scratch (no allocations allowed) ----
__device__ int   g_cnt[3][NN];
__device__ float g_dinv[3][NN];
__device__ int   g_off[NN + 1];
__device__ int   g_cur[NN];
__device__ int   g_bsum[NBLK];
__device__ int   g_bpre[NBLK];
__device__ unsigned g_csr[NE];
__device__ __align__(16) float g_h[3][NN * HID];
__device__ __align__(16) float g_pool[NG * HID];
__device__ float g_pcnt[NG];
// tf32 hi/lo bit-pattern images of W, row-major [k][n]
__device__ __align__(16) unsigned g_Wh32[3][HID * HID];
__device__ __align__(16) unsigned g_Wl32[3][HID * HID];

__device__ __forceinline__ unsigned to_tf32(float v) {
    unsigned u;
    asm("cvt.rna.tf32.f32 %0, %1;" : "=r"(u) : "f"(v));
    return u;
}

// ---------------- init ----------------
__global__ void k_zero() {
    int i = blockIdx.x * blockDim.x + threadIdx.x;
    if (i < NN) { g_cnt[0][i] = 0; g_cnt[1][i] = 0; g_cnt[2][i] = 0; }
    if (i < NG * HID) g_pool[i] = 0.0f;
    if (i < NG) g_pcnt[i] = 0.0f;
}

// ---------------- W prep: f32 -> tf32 hi/lo bit images ----------------
__global__ void k_prepW(const float* __restrict__ W1,
                        const float* __restrict__ W2,
                        const float* __restrict__ W3) {
    int sel = blockIdx.x >> 6;
    int idx = (blockIdx.x & 63) * 256 + threadIdx.x;   // 0..16383
    const float* W = sel == 0 ? W1 : (sel == 1 ? W2 : W3);
    float v = W[idx];
    unsigned uh = to_tf32(v);
    float lo = v - __uint_as_float(uh);
    g_Wh32[sel][idx] = uh;
    g_Wl32[sel][idx] = to_tf32(lo);
}

// ---------------- degree histogram ----------------
__global__ void k_hist(const int* __restrict__ ei,
                       const int* __restrict__ em) {
    int e = blockIdx.x * blockDim.x + threadIdx.x;
    if (e >= NE) return;
    int d = ei[NE + e];
    int m = em[e];
    atomicAdd(&g_cnt[0][d], 1);
    if (m == 1) atomicAdd(&g_cnt[1][d], 1);
    else if (m == 2) atomicAdd(&g_cnt[2][d], 1);
}

// ---------------- scan passes (single channel: total degree) ------------
__global__ void k_scanA() {
    int i = blockIdx.x * 256 + threadIdx.x;
    int lane = threadIdx.x & 31, warp = threadIdx.x >> 5;
    int v = (i < NN) ? g_cnt[0][i] : 0;
#pragma unroll
    for (int o = 16; o; o >>= 1) v += __shfl_xor_sync(0xFFFFFFFFu, v, o);
    __shared__ int ws[8];
    if (lane == 0) ws[warp] = v;
    __syncthreads();
    if (threadIdx.x == 0) {
        int s = 0;
#pragma unroll
        for (int j = 0; j < 8; j++) s += ws[j];
        g_bsum[blockIdx.x] = s;
    }
}

__global__ void k_scanB() {
    __shared__ int sh[256];
    int t = threadIdx.x;
    int v = (t < NBLK) ? g_bsum[t] : 0;
    sh[t] = v;
    __syncthreads();
    for (int d = 1; d < 256; d <<= 1) {
        int u = (t >= d) ? sh[t - d] : 0;
        __syncthreads();
        sh[t] += u;
        __syncthreads();
    }
    if (t < NBLK) g_bpre[t] = sh[t] - v;
    if (t == NBLK - 1) g_off[NN] = sh[t];
}

__global__ void k_scanC() {
    int i = blockIdx.x * 256 + threadIdx.x;
    int lane = threadIdx.x & 31, warp = threadIdx.x >> 5;
    int v = (i < NN) ? g_cnt[0][i] : 0;
    int incl = v;
#pragma unroll
    for (int o = 1; o < 32; o <<= 1) {
        int t = __shfl_up_sync(0xFFFFFFFFu, incl, o);
        if (lane >= o) incl += t;
    }
    __shared__ int ws[8];
    if (lane == 31) ws[warp] = incl;
    __syncthreads();
    if (warp == 0 && lane < 8) {
        int s = ws[lane];
        int si = s;
#pragma unroll
        for (int o = 1; o < 8; o <<= 1) {
            int t = __shfl_up_sync(0xFFu, si, o);
            if (lane >= o) si += t;
        }
        ws[lane] = si - s;
    }
    __syncthreads();
    if (i < NN) {
        int excl = (incl - v) + ws[warp] + g_bpre[blockIdx.x];
        g_off[i] = excl;
        g_cur[i] = excl;
        g_dinv[0][i] = rsqrtf((float)(v + 1));
        g_dinv[1][i] = rsqrtf((float)(g_cnt[1][i] + 1));
        g_dinv[2][i] = rsqrtf((float)(g_cnt[2][i] + 1));
    }
}

// ---------------- CSR scatter (src | mask<<16, single list) ------------
__global__ void k_scatter(const int* __restrict__ ei,
                          const int* __restrict__ em) {
    int e = blockIdx.x * blockDim.x + threadIdx.x;
    if (e >= NE) return;
    int s = ei[e];
    int d = ei[NE + e];
    int m = em[e];
    int pos = atomicAdd(&g_cur[d], 1);
    g_csr[pos] = (unsigned)s | ((unsigned)m << 16);   // s < 50000 < 2^16
}

// ---------------- tensor-core GEMM via mma.sync tf32 (split hi/lo) ----------
// block 64x128, 8 warps (2x4), warp tile 32x32, K-tile 16,
// register-prefetch pipeline: next tile's LDGs overlap current tile's MMAs.
#define MMA_TF32(d, a, b)                                                     \
    asm volatile("mma.sync.aligned.m16n8k8.row.col.f32.tf32.tf32.f32 "        \
        "{%0,%1,%2,%3}, {%4,%5,%6,%7}, {%8,%9}, {%0,%1,%2,%3};"               \
        : "+f"((d)[0]), "+f"((d)[1]), "+f"((d)[2]), "+f"((d)[3])              \
        : "r"((a)[0]), "r"((a)[1]), "r"((a)[2]), "r"((a)[3]),                 \
          "r"((b)[0]), "r"((b)[1]))

__global__ void __launch_bounds__(256, 1)
k_gemm_mma(int inSel, const float* __restrict__ Xext, int wsel) {
    __shared__ unsigned Xh[64][20], Xl[64][20];       // X tile hi/lo, K-tile 16
    __shared__ unsigned Whs[16][136], Wls[16][136];   // W tile hi/lo (pad 136)
    const float* X = (inSel < 0) ? Xext : g_h[inSel];
    const unsigned* __restrict__ Wh = g_Wh32[wsel];
    const unsigned* __restrict__ Wl = g_Wl32[wsel];

    int tid  = threadIdx.x;
    int lane = tid & 31;
    int wid  = tid >> 5;
    int wRow = (wid & 1) * 32;
    int wCol = (wid >> 1) * 32;
    int rowBase = blockIdx.x * 64;

    int lr = lane >> 2;
    int lc = lane & 3;

    // prefetch addressing
    int xrow = tid >> 2, xkq = (tid & 3) * 4;
    int grow = rowBase + xrow;
    bool xvalid = grow < NN;
    int wkr0 = tid >> 5, wn0 = (tid & 31) * 4;   // j = tid
    int wkr1 = wkr0 + 8;                         // j = tid + 256, same n

    float acc[2][4][4];
#pragma unroll
    for (int a = 0; a < 2; a++)
#pragma unroll
        for (int b = 0; b < 4; b++)
#pragma unroll
            for (int c = 0; c < 4; c++) acc[a][b][c] = 0.f;

    float4 xv = make_float4(0.f, 0.f, 0.f, 0.f);
    uint4 wh0, wh1, wl0, wl1;
    // prefetch tile 0
    if (xvalid) xv = *(const float4*)&X[(size_t)grow * HID + xkq];
    wh0 = *(const uint4*)&Wh[wkr0 * HID + wn0];
    wh1 = *(const uint4*)&Wh[wkr1 * HID + wn0];
    wl0 = *(const uint4*)&Wl[wkr0 * HID + wn0];
    wl1 = *(const uint4*)&Wl[wkr1 * HID + wn0];

    for (int t = 0; t < 8; t++) {
        // stage prefetched tile into smem
        {
            unsigned h0 = to_tf32(xv.x), h1 = to_tf32(xv.y),
                     h2 = to_tf32(xv.z), h3 = to_tf32(xv.w);
            *(uint4*)&Xh[xrow][xkq] = make_uint4(h0, h1, h2, h3);
            *(uint4*)&Xl[xrow][xkq] =
                make_uint4(to_tf32(xv.x - __uint_as_float(h0)),
                           to_tf32(xv.y - __uint_as_float(h1)),
                           to_tf32(xv.z - __uint_as_float(h2)),
                           to_tf32(xv.w - __uint_as_float(h3)));
            *(uint4*)&Whs[wkr0][wn0] = wh0;
            *(uint4*)&Whs[wkr1][wn0] = wh1;
            *(uint4*)&Wls[wkr0][wn0] = wl0;
            *(uint4*)&Wls[wkr1][wn0] = wl1;
        }
        __syncthreads();

        // prefetch next tile (LDG latency overlaps compute below)
        if (t < 7) {
            int kt = (t + 1) * 16;
            if (xvalid) xv = *(const float4*)&X[(size_t)grow * HID + kt + xkq];
            wh0 = *(const uint4*)&Wh[(kt + wkr0) * HID + wn0];
            wh1 = *(const uint4*)&Wh[(kt + wkr1) * HID + wn0];
            wl0 = *(const uint4*)&Wl[(kt + wkr0) * HID + wn0];
            wl1 = *(const uint4*)&Wl[(kt + wkr1) * HID + wn0];
        }

#pragma unroll
        for (int ks = 0; ks < 16; ks += 8) {
            unsigned bh[4][2], bl[4][2];
#pragma unroll
            for (int tc = 0; tc < 4; tc++) {
                int n = wCol + tc * 8 + lr;
                bh[tc][0] = Whs[ks + lc][n];
                bh[tc][1] = Whs[ks + lc + 4][n];
                bl[tc][0] = Wls[ks + lc][n];
                bl[tc][1] = Wls[ks + lc + 4][n];
            }
#pragma unroll
            for (int tr = 0; tr < 2; tr++) {
                int r = wRow + tr * 16 + lr;
                unsigned ah[4], al[4];
                ah[0] = Xh[r][ks + lc];       ah[1] = Xh[r + 8][ks + lc];
                ah[2] = Xh[r][ks + lc + 4];   ah[3] = Xh[r + 8][ks + lc + 4];
                al[0] = Xl[r][ks + lc];       al[1] = Xl[r + 8][ks + lc];
                al[2] = Xl[r][ks + lc + 4];   al[3] = Xl[r + 8][ks + lc + 4];
#pragma unroll
                for (int tc = 0; tc < 4; tc++) {
                    MMA_TF32(acc[tr][tc], ah, bh[tc]);
                    MMA_TF32(acc[tr][tc], al, bh[tc]);
                    MMA_TF32(acc[tr][tc], ah, bl[tc]);
                }
            }
        }
        __syncthreads();
    }

    // epilogue
#pragma unroll
    for (int tr = 0; tr < 2; tr++) {
        int r0 = rowBase + wRow + tr * 16 + lr;
#pragma unroll
        for (int tc = 0; tc < 4; tc++) {
            int col = wCol + tc * 8 + 2 * lc;
            if (r0 < NN)
                *(float2*)&g_h[0][(size_t)r0 * HID + col] =
                    make_float2(acc[tr][tc][0], acc[tr][tc][1]);
            if (r0 + 8 < NN)
                *(float2*)&g_h[0][(size_t)(r0 + 8) * HID + col] =
                    make_float2(acc[tr][tc][2], acc[tr][tc][3]);
        }
    }
}

// ---------------- aggregation: lane-parallel edge staging ----------------
__global__ void k_agg(int layer, int outSel,
                      const float* __restrict__ bias,
                      int mode, int do_relu,
                      int doPool, const int* __restrict__ batch) {
    int wi = (blockIdx.x * blockDim.x + threadIdx.x) >> 5;
    if (wi >= NN) return;
    int lane = threadIdx.x & 31;

    const float* __restrict__ dinv = g_dinv[layer];
    float di = dinv[wi];
    int e0 = g_off[wi], e1 = g_off[wi + 1];

    float ax = 0.f, ay = 0.f, az = 0.f, aw = 0.f;
    for (int base = e0; base < e1; base += 32) {
        int idx = base + lane;
        bool valid = idx < e1;
        unsigned p = valid ? g_csr[idx] : 0u;
        int s = (int)(p & 0xFFFFu);
        bool keep = valid && (mode == 0 || (int)(p >> 16) == mode);
        float c = keep ? di * dinv[s] : 0.f;
        unsigned bal = __ballot_sync(0xFFFFFFFFu, keep);
        while (bal) {
            int j = __ffs(bal) - 1;
            bal &= bal - 1;
            float cj = __shfl_sync(0xFFFFFFFFu, c, j);
            int   sj = __shfl_sync(0xFFFFFFFFu, s, j);
            float4 hv = *(const float4*)&g_h[0][(size_t)sj * HID + lane * 4];
            ax += cj * hv.x; ay += cj * hv.y;
            az += cj * hv.z; aw += cj * hv.w;
        }
    }

    float4 hs = *(const float4*)&g_h[0][(size_t)wi * HID + lane * 4];
    float c2 = di * di;
    ax += c2 * hs.x; ay += c2 * hs.y; az += c2 * hs.z; aw += c2 * hs.w;

    float4 bv = *(const float4*)&bias[lane * 4];
    ax += bv.x; ay += bv.y; az += bv.z; aw += bv.w;

    if (do_relu) {
        ax = fmaxf(ax, 0.f); ay = fmaxf(ay, 0.f);
        az = fmaxf(az, 0.f); aw = fmaxf(aw, 0.f);
    }
    float4 o; o.x = ax; o.y = ay; o.z = az; o.w = aw;
    *(float4*)&g_h[outSel][(size_t)wi * HID + lane * 4] = o;

    if (doPool) {
        int g = batch[wi];
        float* base = &g_pool[g * HID + lane * 4];
        atomicAdd(base + 0, ax);
        atomicAdd(base + 1, ay);
        atomicAdd(base + 2, az);
        atomicAdd(base + 3, aw);
        if (lane == 0) atomicAdd(&g_pcnt[g], 1.0f);
    }
}

// ---------------- head ----------------
__global__ void k_final(const float* __restrict__ Wl,
                        const float* __restrict__ bl,
                        float* __restrict__ out) {
    int g = blockIdx.x;
    int lane = threadIdx.x;
    float inv = 1.0f / fmaxf(g_pcnt[g], 1.0f);
    float s = 0.f;
    for (int j = lane; j < HID; j += 32)
        s += g_pool[g * HID + j] * inv * Wl[j];
#pragma unroll
    for (int o = 16; o; o >>= 1) s += __shfl_xor_sync(0xFFFFFFFFu, s, o);
    if (lane == 0) out[g] = s + bl[0];
}

// ---------------- launcher: stream-forked build overlaps GEMM1 ----------
extern "C" void kernel_launch(void* const* d_in, const int* in_sizes, int n_in,
                              void* d_out, int out_size) {
    const float* x     = (const float*)d_in[0];
    const int*   ei    = (const int*)d_in[1];
    const int*   em    = (const int*)d_in[2];
    const int*   batch = (const int*)d_in[3];
    const float* W1 = (const float*)d_in[4];
    const float* b1 = (const float*)d_in[5];
    const float* W2 = (const float*)d_in[6];
    const float* b2 = (const float*)d_in[7];
    const float* W3 = (const float*)d_in[8];
    const float* b3 = (const float*)d_in[9];
    const float* Wl = (const float*)d_in[10];
    const float* bl = (const float*)d_in[11];
    float* out = (float*)d_out;

    const int tb  = 256;
    const int gbN = (NN + tb - 1) / tb;
    const int gbE = (NE + tb - 1) / tb;
    const int gbW = (NN * 32 + tb - 1) / tb;

    // one-time host resources (no device memory involved)
    static cudaStream_t sb = nullptr;
    static cudaEvent_t evFork = nullptr, evJoin = nullptr;
    if (sb == nullptr) {
        cudaStreamCreateWithFlags(&sb, cudaStreamNonBlocking);
        cudaEventCreateWithFlags(&evFork, cudaEventDisableTiming);
        cudaEventCreateWithFlags(&evJoin, cudaEventDisableTiming);
    }

    // main stream: W prep + GEMM1 (independent of CSR build)
    k_prepW   <<<192, 256>>>(W1, W2, W3);
    k_gemm_mma<<<GEMM_CTAS, 256>>>(-1, x, 0);

    // fork: CSR build runs concurrently on stream sb
    cudaEventRecord(evFork, 0);
    cudaStreamWaitEvent(sb, evFork, 0);
    k_zero   <<<gbN, tb, 0, sb>>>();
    k_hist   <<<gbE, tb, 0, sb>>>(ei, em);
    k_scanA  <<<NBLK, 256, 0, sb>>>();
    k_scanB  <<<1, 256, 0, sb>>>();
    k_scanC  <<<NBLK, 256, 0, sb>>>();
    k_scatter<<<gbE, tb, 0, sb>>>(ei, em);
    cudaEventRecord(evJoin, sb);

    // join before the first aggregation
    cudaStreamWaitEvent(0, evJoin, 0);

    // layer 1: g_h[0] -> g_h[1] (relu, all edges)
    k_agg <<<gbW, tb>>>(0, 1, b1, 0, 1, 0, batch);
    // layer 2
    k_gemm_mma<<<GEMM_CTAS, 256>>>(1, x, 1);
    k_agg <<<gbW, tb>>>(1, 2, b2, 1, 1, 0, batch);
    // layer 3 + fused pool
    k_gemm_mma<<<GEMM_CTAS, 256>>>(2, x, 2);
    k_agg <<<gbW, tb>>>(2, 1, b3, 2, 0, 1, batch);

    k_final<<<NG, 32>>>(Wl, bl, out);
}